// round 16
// baseline (speedup 1.0000x reference)
#include <cuda_runtime.h>
#include <cuda_fp16.h>
#include <cstdint>
#include <cstddef>

#define D_DIM   1024
#define NBATCH  16
#define NROWS   (NBATCH * D_DIM)

#define BM 128
#define BN 128
#define BK 64                  // fp16 per K-chunk = 128B row (SW128)
#define NSTG 3
#define NITER 16               // chunks per tile

#define TILE_BYTES  (BM * 128)           // 16 KB
#define STAGE_BYTES (2 * TILE_BYTES)     // 32 KB
#define SMEM_BYTES  (NSTG * STAGE_BYTES) // 96 KB

#define NTILES_TOT  1024
#define GRID_CTAS   296                  // 2 CTAs/SM * 148 SMs, persistent

// fp16 normalized-row scratch (allocation-free: __device__ globals)
__device__ __half g_ra[(size_t)NBATCH * D_DIM * D_DIM];
__device__ __half g_rb[(size_t)NBATCH * D_DIM * D_DIM];

// ---------------------------------------------------------------- helpers
static __device__ __forceinline__ uint32_t smem_u32(const void* p) {
    uint32_t a;
    asm("{ .reg .u64 t; cvta.to.shared.u64 t, %1; cvt.u32.u64 %0, t; }"
        : "=r"(a) : "l"(p));
    return a;
}
static __device__ __forceinline__ uint32_t sw128(uint32_t o) {
    return o ^ ((o >> 3) & 0x70u);
}
static __device__ __forceinline__ void cp16(uint32_t dst, const void* src) {
    asm volatile("cp.async.cg.shared.global [%0], [%1], 16;"
                 :: "r"(dst), "l"(src) : "memory");
}
static __device__ __forceinline__ void ldmatrix_x4(uint32_t* r, uint32_t addr) {
    asm volatile("ldmatrix.sync.aligned.m8n8.x4.shared.b16 {%0,%1,%2,%3}, [%4];"
                 : "=r"(r[0]), "=r"(r[1]), "=r"(r[2]), "=r"(r[3]) : "r"(addr));
}
static __device__ __forceinline__ void mma16816(float* d, const uint32_t* a,
                                                const uint32_t* b) {
    asm volatile(
        "mma.sync.aligned.m16n8k16.row.col.f32.f16.f16.f32 "
        "{%0,%1,%2,%3}, {%4,%5,%6,%7}, {%8,%9}, {%0,%1,%2,%3};"
        : "+f"(d[0]), "+f"(d[1]), "+f"(d[2]), "+f"(d[3])
        : "r"(a[0]), "r"(a[1]), "r"(a[2]), "r"(a[3]), "r"(b[0]), "r"(b[1]));
}
// Streaming store: output is never re-read -> evict-first, protect panels in L2.
static __device__ __forceinline__ void stcs2(float* p, float x, float y) {
    asm volatile("st.global.cs.v2.f32 [%0], {%1, %2};"
                 :: "l"(p), "f"(x), "f"(y) : "memory");
}

// ---------------------------------------------------------------- normalize
__global__ void __launch_bounds__(128) norm_kernel(const float* __restrict__ a,
                                                   const float* __restrict__ b,
                                                   const float* __restrict__ w) {
    const int row = blockIdx.x;
    const float* src = (blockIdx.y == 0) ? a : b;
    __half* dst = (blockIdx.y == 0) ? g_ra : g_rb;
    const int t = threadIdx.x;

    const float4* s4 = reinterpret_cast<const float4*>(src + (size_t)row * D_DIM);
    const float4* w4 = reinterpret_cast<const float4*>(w);

    float4 x0 = s4[t];       float4 w0 = w4[t];
    float4 x1 = s4[t + 128]; float4 w1 = w4[t + 128];
    float4 v0, v1;
    v0.x = x0.x * w0.x; v0.y = x0.y * w0.y; v0.z = x0.z * w0.z; v0.w = x0.w * w0.w;
    v1.x = x1.x * w1.x; v1.y = x1.y * w1.y; v1.z = x1.z * w1.z; v1.w = x1.w * w1.w;

    float sum = v0.x * v0.x + v0.y * v0.y + v0.z * v0.z + v0.w * v0.w
              + v1.x * v1.x + v1.y * v1.y + v1.z * v1.z + v1.w * v1.w;
#pragma unroll
    for (int o = 16; o > 0; o >>= 1) sum += __shfl_xor_sync(0xFFFFFFFFu, sum, o);

    __shared__ float red[4];
    if ((t & 31) == 0) red[t >> 5] = sum;
    __syncthreads();
    float tot = red[0] + red[1] + red[2] + red[3];
    float s = rsqrtf(fmaxf(tot, 1e-12f));

    __half2* d2 = reinterpret_cast<__half2*>(dst + (size_t)row * D_DIM);
    d2[2 * t + 0]         = __floats2half2_rn(v0.x * s, v0.y * s);
    d2[2 * t + 1]         = __floats2half2_rn(v0.z * s, v0.w * s);
    d2[2 * (t + 128) + 0] = __floats2half2_rn(v1.x * s, v1.y * s);
    d2[2 * (t + 128) + 1] = __floats2half2_rn(v1.z * s, v1.w * s);
}

// ---------------------------------------------------------------- GEMM
// Persistent: 296 CTAs, each handles tiles bid, bid+296, ... The cp.async
// ring runs over a GLOBAL chunk index (stage = gc % 3), so the pipeline never
// drains at tile boundaries: next tile's first chunks load under the current
// tile's last MMAs and epilogue stores.
__global__ void __launch_bounds__(128, 2) gemm_kernel(float* __restrict__ out) {
    extern __shared__ char smem[];
    const uint32_t sb = smem_u32(smem);
    const int tid  = threadIdx.x;
    const int wid  = tid >> 5;
    const int lane = tid & 31;
    const int wm   = wid & 1;        // 2 warps along M: 64 rows each
    const int wn   = wid >> 1;       // 2 warps along N: 64 cols each
    const int bid  = blockIdx.x;

    const int ntiles  = (NTILES_TOT - 1 - bid) / GRID_CTAS + 1;   // 3 or 4
    const int nchunks = ntiles * NITER;

    // Chunk loader: global chunk c -> (tile, k-offset); always commits a
    // group (possibly empty) to keep wait_group-1 semantics exact.
    auto load_chunk = [&](int c) {
        if (c < nchunks) {
            const int t   = bid + (c >> 4) * GRID_CTAS;
            const int kof = (c & 15) * BK;
            const __half* gA = g_ra + ((size_t)(t >> 6) << 20)
                             + (size_t)(((t >> 3) & 7) * BM) * D_DIM;
            const __half* gB = g_rb + ((size_t)(t >> 6) << 20)
                             + (size_t)((t & 7) * BN) * D_DIM;
            const uint32_t stg = sb + (uint32_t)(c % NSTG) * STAGE_BYTES;
#pragma unroll
            for (int i = 0; i < 8; i++) {
                int q = i * 128 + tid;
                int row = q >> 3;
                int colb = (q & 7) * 16;
                uint32_t so = sw128((uint32_t)(row * 128 + colb));
                cp16(stg + so,
                     (const char*)(gA + (size_t)row * D_DIM + kof) + colb);
                cp16(stg + TILE_BYTES + so,
                     (const char*)(gB + (size_t)row * D_DIM + kof) + colb);
            }
        }
        asm volatile("cp.async.commit_group;" ::: "memory");
    };

    float acc[4][8][4];
#pragma unroll
    for (int i = 0; i < 4; i++)
#pragma unroll
        for (int j = 0; j < 8; j++)
#pragma unroll
            for (int v = 0; v < 4; v++) acc[i][j][v] = 0.0f;

    // Swizzled ldmatrix bases; kb = kk*32 occupies bits 5-6 which are zero in
    // the unswizzled base, so sw128(base+kb) == sw128(base) ^ kb.
    const int aRow  = lane & 15;
    const int aColb = (lane >> 4) << 4;
    const int bRow  = ((lane >> 4) << 3) + (lane & 7);
    const int bColb = ((lane >> 3) & 1) << 4;

    uint32_t aOff[4], bOff[4];
#pragma unroll
    for (int mt = 0; mt < 4; mt++)
        aOff[mt] = sw128((uint32_t)((wm * 64 + mt * 16 + aRow) * 128 + aColb));
#pragma unroll
    for (int nq = 0; nq < 4; nq++)
        bOff[nq] = sw128((uint32_t)((wn * 64 + nq * 16 + bRow) * 128 + bColb))
                 + TILE_BYTES;

    uint32_t af[2][4][4], bf[2][4][4];

#define LD_FRAGS(buf, sT, kk)                                              \
    do {                                                                   \
        const uint32_t kb_ = (kk) * 32;                                    \
        _Pragma("unroll")                                                  \
        for (int mt_ = 0; mt_ < 4; mt_++)                                  \
            ldmatrix_x4(af[buf][mt_], (sT) + (aOff[mt_] ^ kb_));           \
        _Pragma("unroll")                                                  \
        for (int nq_ = 0; nq_ < 4; nq_++)                                  \
            ldmatrix_x4(bf[buf][nq_], (sT) + (bOff[nq_] ^ kb_));           \
    } while (0)

#define MMA_ALL(buf)                                                       \
    do {                                                                   \
        _Pragma("unroll")                                                  \
        for (int nq_ = 0; nq_ < 4; nq_++)                                  \
            _Pragma("unroll")                                              \
            for (int mt_ = 0; mt_ < 4; mt_++) {                            \
                mma16816(acc[mt_][2 * nq_ + 0], af[buf][mt_],              \
                         &bf[buf][nq_][0]);                                \
                mma16816(acc[mt_][2 * nq_ + 1], af[buf][mt_],              \
                         &bf[buf][nq_][2]);                                \
            }                                                              \
    } while (0)

    // prologue: chunks 0,1 in flight; pre-arm buffer 0 with chunk0 kk=0
    load_chunk(0);
    load_chunk(1);
    asm volatile("cp.async.wait_group 1;" ::: "memory");   // chunk 0 resident
    __syncthreads();
    LD_FRAGS(0, sb + 0 * STAGE_BYTES, 0);

#pragma unroll 1
    for (int gc = 0; gc < nchunks; gc++) {
        const uint32_t sT = sb + (uint32_t)(gc % NSTG) * STAGE_BYTES;

        // Writes stage (gc+2)%3 == (gc-1)%3: last read in iteration gc-1,
        // strictly before the barrier at the tail of iteration gc-1.
        load_chunk(gc + 2);

        // buffer0 already holds kk=0 fragments (prefetched last iteration)
        LD_FRAGS(1, sT, 1);
        MMA_ALL(0);
        LD_FRAGS(0, sT, 2);
        MMA_ALL(1);
        LD_FRAGS(1, sT, 3);
        MMA_ALL(0);

        if (gc + 1 < nchunks) {
            // Committed groups: 0..gc+2; wait_group 1 => chunk gc+1 resident.
            // Barrier: all warps finished reading stages gc%3 and (gc-1)%3.
            asm volatile("cp.async.wait_group 1;" ::: "memory");
            __syncthreads();
            // Prefetch next chunk's kk=0 under the trailing MMA block
            // (works across tile boundaries: chunk gc+1 may be next tile's k=0).
            LD_FRAGS(0, sb + (uint32_t)((gc + 1) % NSTG) * STAGE_BYTES, 0);
        }
        MMA_ALL(1);

        // ---- tile boundary: epilogue + acc reset (stores overlap the
        // already-in-flight cp.asyncs of the next tile's chunks)
        if ((gc & 15) == 15) {
            const int t = bid + (gc >> 4) * GRID_CTAS;
            const int bm0 = ((t >> 3) & 7) * BM;
            const int bn0 = (t & 7) * BN;
            float* oB = out + ((size_t)(t >> 6) << 20);
#pragma unroll
            for (int mt = 0; mt < 4; mt++) {
                int row = bm0 + wm * 64 + mt * 16 + (lane >> 2);
#pragma unroll
                for (int nt = 0; nt < 8; nt++) {
                    int col = bn0 + wn * 64 + nt * 8 + (lane & 3) * 2;
                    stcs2(oB + (size_t)row * D_DIM + col,
                          acc[mt][nt][0], acc[mt][nt][1]);
                    stcs2(oB + (size_t)(row + 8) * D_DIM + col,
                          acc[mt][nt][2], acc[mt][nt][3]);
                    acc[mt][nt][0] = 0.0f; acc[mt][nt][1] = 0.0f;
                    acc[mt][nt][2] = 0.0f; acc[mt][nt][3] = 0.0f;
                }
            }
        }
    }
}

// ---------------------------------------------------------------- launch
extern "C" void kernel_launch(void* const* d_in, const int* in_sizes, int n_in,
                              void* d_out, int out_size) {
    const float* a = (const float*)d_in[0];
    const float* b = (const float*)d_in[1];
    const float* w = (const float*)d_in[2];
    float* out = (float*)d_out;

    norm_kernel<<<dim3(NROWS, 2, 1), 128>>>(a, b, w);

    cudaFuncSetAttribute(gemm_kernel, cudaFuncAttributeMaxDynamicSharedMemorySize,
                         SMEM_BYTES);
    gemm_kernel<<<GRID_CTAS, 128, SMEM_BYTES>>>(out);
}

// round 17
// speedup vs baseline: 1.0778x; 1.0778x over previous
#include <cuda_runtime.h>
#include <cuda_fp16.h>
#include <cstdint>
#include <cstddef>

#define D_DIM   1024
#define NBATCH  16
#define NROWS   (NBATCH * D_DIM)

#define BM 128
#define BN 128
#define BK 64                  // fp16 per K-chunk = 128B row (SW128)
#define NSTG 3

#define TILE_BYTES  (BM * 128)           // 16 KB
#define STAGE_BYTES (2 * TILE_BYTES)     // 32 KB
#define SMEM_BYTES  (NSTG * STAGE_BYTES) // 96 KB

#define NTILES_TOT  1024
#define GRID_CTAS   296                  // 2 CTAs/SM * 148 SMs, persistent

// fp16 normalized-row scratch (allocation-free: __device__ globals)
__device__ __half g_ra[(size_t)NBATCH * D_DIM * D_DIM];
__device__ __half g_rb[(size_t)NBATCH * D_DIM * D_DIM];

// ---------------------------------------------------------------- helpers
static __device__ __forceinline__ uint32_t smem_u32(const void* p) {
    uint32_t a;
    asm("{ .reg .u64 t; cvta.to.shared.u64 t, %1; cvt.u32.u64 %0, t; }"
        : "=r"(a) : "l"(p));
    return a;
}
static __device__ __forceinline__ uint32_t sw128(uint32_t o) {
    return o ^ ((o >> 3) & 0x70u);
}
static __device__ __forceinline__ void cp16(uint32_t dst, const void* src) {
    asm volatile("cp.async.cg.shared.global [%0], [%1], 16;"
                 :: "r"(dst), "l"(src) : "memory");
}
static __device__ __forceinline__ void ldmatrix_x4(uint32_t* r, uint32_t addr) {
    asm volatile("ldmatrix.sync.aligned.m8n8.x4.shared.b16 {%0,%1,%2,%3}, [%4];"
                 : "=r"(r[0]), "=r"(r[1]), "=r"(r[2]), "=r"(r[3]) : "r"(addr));
}
static __device__ __forceinline__ void mma16816(float* d, const uint32_t* a,
                                                const uint32_t* b) {
    asm volatile(
        "mma.sync.aligned.m16n8k16.row.col.f32.f16.f16.f32 "
        "{%0,%1,%2,%3}, {%4,%5,%6,%7}, {%8,%9}, {%0,%1,%2,%3};"
        : "+f"(d[0]), "+f"(d[1]), "+f"(d[2]), "+f"(d[3])
        : "r"(a[0]), "r"(a[1]), "r"(a[2]), "r"(a[3]), "r"(b[0]), "r"(b[1]));
}
// Streaming store: output is never re-read -> evict-first, protect panels in L2.
static __device__ __forceinline__ void stcs2(float* p, float x, float y) {
    asm volatile("st.global.cs.v2.f32 [%0], {%1, %2};"
                 :: "l"(p), "f"(x), "f"(y) : "memory");
}

// ---------------------------------------------------------------- normalize
__global__ void __launch_bounds__(128) norm_kernel(const float* __restrict__ a,
                                                   const float* __restrict__ b,
                                                   const float* __restrict__ w) {
    const int row = blockIdx.x;
    const float* src = (blockIdx.y == 0) ? a : b;
    __half* dst = (blockIdx.y == 0) ? g_ra : g_rb;
    const int t = threadIdx.x;

    const float4* s4 = reinterpret_cast<const float4*>(src + (size_t)row * D_DIM);
    const float4* w4 = reinterpret_cast<const float4*>(w);

    float4 x0 = s4[t];       float4 w0 = w4[t];
    float4 x1 = s4[t + 128]; float4 w1 = w4[t + 128];
    float4 v0, v1;
    v0.x = x0.x * w0.x; v0.y = x0.y * w0.y; v0.z = x0.z * w0.z; v0.w = x0.w * w0.w;
    v1.x = x1.x * w1.x; v1.y = x1.y * w1.y; v1.z = x1.z * w1.z; v1.w = x1.w * w1.w;

    float sum = v0.x * v0.x + v0.y * v0.y + v0.z * v0.z + v0.w * v0.w
              + v1.x * v1.x + v1.y * v1.y + v1.z * v1.z + v1.w * v1.w;
#pragma unroll
    for (int o = 16; o > 0; o >>= 1) sum += __shfl_xor_sync(0xFFFFFFFFu, sum, o);

    __shared__ float red[4];
    if ((t & 31) == 0) red[t >> 5] = sum;
    __syncthreads();
    float tot = red[0] + red[1] + red[2] + red[3];
    float s = rsqrtf(fmaxf(tot, 1e-12f));

    __half2* d2 = reinterpret_cast<__half2*>(dst + (size_t)row * D_DIM);
    d2[2 * t + 0]         = __floats2half2_rn(v0.x * s, v0.y * s);
    d2[2 * t + 1]         = __floats2half2_rn(v0.z * s, v0.w * s);
    d2[2 * (t + 128) + 0] = __floats2half2_rn(v1.x * s, v1.y * s);
    d2[2 * (t + 128) + 1] = __floats2half2_rn(v1.z * s, v1.w * s);
}

// ---------------------------------------------------------------- GEMM
// Persistent (296 CTAs = 2/SM), cross-tile software pipeline: the cp.async
// ring runs over a global chunk sequence (stage rotates by register, no
// modulo), so next tile's first chunks load under the current tile's last
// MMAs and the epilogue stores. All hot-loop indexing is incremental.
__global__ void __launch_bounds__(128, 2) gemm_kernel(float* __restrict__ out) {
    extern __shared__ char smem[];
    const uint32_t sb = smem_u32(smem);
    const int tid  = threadIdx.x;
    const int wid  = tid >> 5;
    const int lane = tid & 31;
    const int wm   = wid & 1;        // 2 warps along M: 64 rows each
    const int wn   = wid >> 1;       // 2 warps along N: 64 cols each
    const int bid  = blockIdx.x;

    const int ntiles = (NTILES_TOT - 1 - bid) / GRID_CTAS + 1;   // 3 or 4
    int t = bid;

    // Byte pointers to the NEXT chunk to load (advance 128B per chunk).
    const char* ldA = (const char*)g_ra + ((size_t)(t >> 6) << 21)
                    + (size_t)(((t >> 3) & 7) * BM) * (D_DIM * 2);
    const char* ldB = (const char*)g_rb + ((size_t)(t >> 6) << 21)
                    + (size_t)((t & 7) * BN) * (D_DIM * 2);

    // 16B-segment loader from running byte pointers.
    auto load16 = [&](const char* lA, const char* lB, uint32_t stg) {
#pragma unroll
        for (int i = 0; i < 8; i++) {
            int q = i * 128 + tid;
            int row = q >> 3;                 // 0..127
            int colb = (q & 7) * 16;
            uint32_t so = sw128((uint32_t)(row * 128 + colb));
            cp16(stg + so,              lA + (size_t)row * (D_DIM * 2) + colb);
            cp16(stg + TILE_BYTES + so, lB + (size_t)row * (D_DIM * 2) + colb);
        }
    };

    float acc[4][8][4];
#pragma unroll
    for (int i = 0; i < 4; i++)
#pragma unroll
        for (int j = 0; j < 8; j++)
#pragma unroll
            for (int v = 0; v < 4; v++) acc[i][j][v] = 0.0f;

    // Swizzled ldmatrix bases; kb = kk*32 occupies bits 5-6 which are zero in
    // the unswizzled base, so sw128(base+kb) == sw128(base) ^ kb.
    const int aRow  = lane & 15;
    const int aColb = (lane >> 4) << 4;
    const int bRow  = ((lane >> 4) << 3) + (lane & 7);
    const int bColb = ((lane >> 3) & 1) << 4;

    uint32_t aOff[4], bOff[4];
#pragma unroll
    for (int mt = 0; mt < 4; mt++)
        aOff[mt] = sw128((uint32_t)((wm * 64 + mt * 16 + aRow) * 128 + aColb));
#pragma unroll
    for (int nq = 0; nq < 4; nq++)
        bOff[nq] = sw128((uint32_t)((wn * 64 + nq * 16 + bRow) * 128 + bColb))
                 + TILE_BYTES;

    uint32_t af[2][4][4], bf[2][4][4];

#define LD_FRAGS(buf, sT_, kk)                                             \
    do {                                                                   \
        const uint32_t kb_ = (kk) * 32;                                    \
        _Pragma("unroll")                                                  \
        for (int mt_ = 0; mt_ < 4; mt_++)                                  \
            ldmatrix_x4(af[buf][mt_], (sT_) + (aOff[mt_] ^ kb_));          \
        _Pragma("unroll")                                                  \
        for (int nq_ = 0; nq_ < 4; nq_++)                                  \
            ldmatrix_x4(bf[buf][nq_], (sT_) + (bOff[nq_] ^ kb_));          \
    } while (0)

#define MMA_ALL(buf)                                                       \
    do {                                                                   \
        _Pragma("unroll")                                                  \
        for (int nq_ = 0; nq_ < 4; nq_++)                                  \
            _Pragma("unroll")                                              \
            for (int mt_ = 0; mt_ < 4; mt_++) {                            \
                mma16816(acc[mt_][2 * nq_ + 0], af[buf][mt_],              \
                         &bf[buf][nq_][0]);                                \
                mma16816(acc[mt_][2 * nq_ + 1], af[buf][mt_],              \
                         &bf[buf][nq_][2]);                                \
            }                                                              \
    } while (0)

    // prologue: chunks 0,1 of tile bid in flight; pre-arm buffer 0 (kk=0)
    load16(ldA, ldB, sb);
    asm volatile("cp.async.commit_group;" ::: "memory");
    load16(ldA + 128, ldB + 128, sb + STAGE_BYTES);
    asm volatile("cp.async.commit_group;" ::: "memory");
    ldA += 256; ldB += 256;                  // now points at chunk 2
    asm volatile("cp.async.wait_group 1;" ::: "memory");   // chunk 0 resident
    __syncthreads();
    LD_FRAGS(0, sb, 0);

    uint32_t sT = sb;                        // compute stage (current chunk)

#pragma unroll 1
    for (int ti = 0; ti < ntiles; ti++) {
        const bool more = (ti + 1 < ntiles);

#pragma unroll 1
        for (int it = 0; it < 16; it++) {
            // Write stage = stage+2 mod 3 = stage-1 mod 3 (register rotate).
            const uint32_t sW = (sT == sb) ? (sb + 2 * STAGE_BYTES)
                                           : (sT - STAGE_BYTES);
            // Load chunk gc+2. At it==14/15 that is the NEXT tile's chunk
            // 0/1; switch base pointers once at it==14 (off critical path).
            if (it == 14 && more) {
                const int t2 = t + GRID_CTAS;
                ldA = (const char*)g_ra + ((size_t)(t2 >> 6) << 21)
                    + (size_t)(((t2 >> 3) & 7) * BM) * (D_DIM * 2);
                ldB = (const char*)g_rb + ((size_t)(t2 >> 6) << 21)
                    + (size_t)((t2 & 7) * BN) * (D_DIM * 2);
            }
            if (it < 14 || more) {
                load16(ldA, ldB, sW);
                ldA += 128; ldB += 128;
            }
            // Commit unconditionally (possibly empty) so wait_group 1 always
            // means "chunk gc+1 resident" — same invariant as R15.
            asm volatile("cp.async.commit_group;" ::: "memory");

            // buffer0 already holds this chunk's kk=0 (prefetched earlier)
            LD_FRAGS(1, sT, 1);
            MMA_ALL(0);
            LD_FRAGS(0, sT, 2);
            MMA_ALL(1);
            LD_FRAGS(1, sT, 3);
            MMA_ALL(0);

            const uint32_t sN = (sT == sb + 2 * STAGE_BYTES)
                              ? sb : (sT + STAGE_BYTES);
            if (it < 15 || more) {
                // Barrier: all warps finished reading stages sT and sT-1;
                // chunk gc+1 resident after this wait. Prefetch its kk=0
                // under the trailing MMA block (crosses tile boundaries).
                asm volatile("cp.async.wait_group 1;" ::: "memory");
                __syncthreads();
                LD_FRAGS(0, sN, 0);
            }
            MMA_ALL(1);
            sT = sN;
        }

        // ---- tile epilogue: stores overlap next tile's in-flight cp.asyncs
        {
            const int bm0 = ((t >> 3) & 7) * BM;
            const int bn0 = (t & 7) * BN;
            float* oB = out + ((size_t)(t >> 6) << 20);
#pragma unroll
            for (int mt = 0; mt < 4; mt++) {
                int row = bm0 + wm * 64 + mt * 16 + (lane >> 2);
#pragma unroll
                for (int nt = 0; nt < 8; nt++) {
                    int col = bn0 + wn * 64 + nt * 8 + (lane & 3) * 2;
                    stcs2(oB + (size_t)row * D_DIM + col,
                          acc[mt][nt][0], acc[mt][nt][1]);
                    stcs2(oB + (size_t)(row + 8) * D_DIM + col,
                          acc[mt][nt][2], acc[mt][nt][3]);
                    acc[mt][nt][0] = 0.0f; acc[mt][nt][1] = 0.0f;
                    acc[mt][nt][2] = 0.0f; acc[mt][nt][3] = 0.0f;
                }
            }
        }
        t += GRID_CTAS;
    }
}

// ---------------------------------------------------------------- launch
extern "C" void kernel_launch(void* const* d_in, const int* in_sizes, int n_in,
                              void* d_out, int out_size) {
    const float* a = (const float*)d_in[0];
    const float* b = (const float*)d_in[1];
    const float* w = (const float*)d_in[2];
    float* out = (float*)d_out;

    norm_kernel<<<dim3(NROWS, 2, 1), 128>>>(a, b, w);

    cudaFuncSetAttribute(gemm_kernel, cudaFuncAttributeMaxDynamicSharedMemorySize,
                         SMEM_BYTES);
    gemm_kernel<<<GRID_CTAS, 128, SMEM_BYTES>>>(out);
}